// round 10
// baseline (speedup 1.0000x reference)
#include <cuda_runtime.h>
#include <cuda_bf16.h>
#include <cstdint>

// BiLinearInterpolation (spatial transformer sampler)
// X:     [B=16, H=512, W=512, C=16] float32  (channels-last)
// theta: [B=16, 6]                  float32
// out:   [B=16, 256, 256, 16]       float32
//
// Numerics (FROZEN — verified rel_err 2.777e-5):
//  - linspace: g = rn(-1 + rn(i * rn(2/255)))
//  - einsum:   sg = rn(fma(t1,gy, rn(t0*gx)) + t2)   (cublas ascending-K)
//  - scale:    x  = rn(rn(sg+1) * 256)
//  - trunc-to-int, clamp, weights = rn(rn(sub)*rn(sub))  (no fma)
//  - blend:    ((rn(wa*pa)+rn(wb*pb))+rn(wc*pc))+rn(wd*pd)  (no fma)
//
// Perf layout: lanes 4k..4k+3 share a pixel (wavefront-optimal). Each thread
// handles FOUR pixels (same batch, rows r, r+64, r+128, r+192) with all 16
// corner loads issued up front (MLP=16). 32-bit address arithmetic.

static constexpr int B     = 16;
static constexpr int H     = 512;
static constexpr int W     = 512;
static constexpr int OUT_H = 256;
static constexpr int OUT_W = 256;
static constexpr int NPIX  = OUT_H * OUT_W;            // 65536
static constexpr int C4    = 4;                        // float4 quarters
static constexpr int PPT   = 4;                        // pixels per thread

__device__ __forceinline__ float4 blend_exact(float wa, float wb, float wc, float wd,
                                              float4 pa, float4 pb, float4 pc, float4 pd)
{
    float4 o;
    o.x = __fadd_rn(__fadd_rn(__fadd_rn(__fmul_rn(wa, pa.x), __fmul_rn(wb, pb.x)),
                              __fmul_rn(wc, pc.x)), __fmul_rn(wd, pd.x));
    o.y = __fadd_rn(__fadd_rn(__fadd_rn(__fmul_rn(wa, pa.y), __fmul_rn(wb, pb.y)),
                              __fmul_rn(wc, pc.y)), __fmul_rn(wd, pd.y));
    o.z = __fadd_rn(__fadd_rn(__fadd_rn(__fmul_rn(wa, pa.z), __fmul_rn(wb, pb.z)),
                              __fmul_rn(wc, pc.z)), __fmul_rn(wd, pd.z));
    o.w = __fadd_rn(__fadd_rn(__fadd_rn(__fmul_rn(wa, pa.w), __fmul_rn(wb, pb.w)),
                              __fmul_rn(wc, pc.w)), __fmul_rn(wd, pd.w));
    return o;
}

struct PixInfo {
    unsigned ia, ib, ic, id;   // float4 indices
    float wa, wb, wc, wd;
};

__device__ __forceinline__ PixInfo pixel_info(float x, float y, unsigned baseb, unsigned c4)
{
    int x0 = (int)x;           // cvt.rzi — trunc toward zero
    int y0 = (int)y;
    int x1 = x0 + 1;
    int y1 = y0 + 1;
    x0 = min(max(x0, 0), W - 1);
    x1 = min(max(x1, 0), W - 1);
    y0 = min(max(y0, 0), H - 1);
    y1 = min(max(y1, 0), H - 1);

    const float x0f = (float)x0, x1f = (float)x1;
    const float y0f = (float)y0, y1f = (float)y1;

    const float dxa = __fsub_rn(x1f, x);
    const float dxb = __fsub_rn(x, x0f);
    const float dya = __fsub_rn(y1f, y);
    const float dyb = __fsub_rn(y, y0f);

    PixInfo p;
    p.wa = __fmul_rn(dxa, dya);
    p.wb = __fmul_rn(dxa, dyb);
    p.wc = __fmul_rn(dxb, dya);
    p.wd = __fmul_rn(dxb, dyb);

    const unsigned r0 = baseb + (unsigned)y0 * W;
    const unsigned r1 = baseb + (unsigned)y1 * W;
    p.ia = (r0 + (unsigned)x0) * C4 + c4;
    p.ib = (r1 + (unsigned)x0) * C4 + c4;
    p.ic = (r0 + (unsigned)x1) * C4 + c4;
    p.id = (r1 + (unsigned)x1) * C4 + c4;
    return p;
}

__global__ __launch_bounds__(256)
void bilinear_sampler_kernel(const float* __restrict__ X,
                             const float* __restrict__ theta,
                             float* __restrict__ out)
{
    const unsigned tid = blockIdx.x * blockDim.x + threadIdx.x;
    // 1,048,576 threads; each does 4 pixels: (b, row + 64*j, col), j=0..3

    const unsigned c4  = tid & 3u;
    const unsigned idx = tid >> 2;             // [0, 262144)
    const unsigned b   = idx >> 14;            // / 16384
    const unsigned rem = idx & 16383u;
    const unsigned row = rem >> 8;             // [0, 64)
    const unsigned col = rem & 255u;

    const float DELTA = 2.0f / 255.0f;
    const float gx = __fadd_rn(-1.0f, __fmul_rn((float)col, DELTA));

    const float* th = theta + b * 6;
    const float t0 = __ldg(th + 0), t1 = __ldg(th + 1), t2 = __ldg(th + 2);
    const float t3 = __ldg(th + 3), t4 = __ldg(th + 4), t5 = __ldg(th + 5);

    const float m0x = __fmul_rn(t0, gx);       // shared across all 4 pixels
    const float m1x = __fmul_rn(t3, gx);

    const unsigned baseb = b * (unsigned)(H * W);
    const float4* Xf4 = (const float4*)X;

    PixInfo P[PPT];
    #pragma unroll
    for (int j = 0; j < PPT; j++) {
        const float gy  = __fadd_rn(-1.0f, __fmul_rn((float)(row + 64u * j), DELTA));
        const float sg0 = __fadd_rn(__fmaf_rn(t1, gy, m0x), t2);
        const float sg1 = __fadd_rn(__fmaf_rn(t4, gy, m1x), t5);
        const float x   = __fmul_rn(__fadd_rn(sg0, 1.0f), 256.0f);
        const float y   = __fmul_rn(__fadd_rn(sg1, 1.0f), 256.0f);
        P[j] = pixel_info(x, y, baseb, c4);
    }

    // 16 independent corner loads up front (MLP=16)
    float4 pa[PPT], pb[PPT], pc[PPT], pd[PPT];
    #pragma unroll
    for (int j = 0; j < PPT; j++) {
        pa[j] = __ldg(Xf4 + P[j].ia);
        pb[j] = __ldg(Xf4 + P[j].ib);
        pc[j] = __ldg(Xf4 + P[j].ic);
        pd[j] = __ldg(Xf4 + P[j].id);
    }

    // output float4 index: (b*65536 + row*256 + col)*4 + c4, row step 64 -> +65536
    const unsigned o0 = (b * (unsigned)NPIX + row * 256u + col) * 4u + c4;
    #pragma unroll
    for (int j = 0; j < PPT; j++) {
        const float4 o = blend_exact(P[j].wa, P[j].wb, P[j].wc, P[j].wd,
                                     pa[j], pb[j], pc[j], pd[j]);
        ((float4*)out)[o0 + 65536u * j] = o;
    }
}

extern "C" void kernel_launch(void* const* d_in, const int* in_sizes, int n_in,
                              void* d_out, int out_size)
{
    const float* X     = (const float*)d_in[0];
    const float* theta = (const float*)d_in[1];
    float* out         = (float*)d_out;

    const int total = B * NPIX * C4 / PPT;   // 1,048,576 threads
    const int tpb = 256;
    bilinear_sampler_kernel<<<total / tpb, tpb>>>(X, theta, out);
}

// round 11
// speedup vs baseline: 1.1619x; 1.1619x over previous
#include <cuda_runtime.h>
#include <cuda_bf16.h>
#include <cstdint>

// BiLinearInterpolation (spatial transformer sampler)
// X:     [B=16, H=512, W=512, C=16] float32  (channels-last)
// theta: [B=16, 6]                  float32
// out:   [B=16, 256, 256, 16]       float32
//
// Numerics (FROZEN — verified rel_err 2.777e-5):
//  - linspace: g = rn(-1 + rn(i * rn(2/255)))
//  - einsum:   sg = rn(fma(t1,gy, rn(t0*gx)) + t2)   (cublas ascending-K)
//  - scale:    x  = rn(rn(sg+1) * 256)
//  - trunc-to-int, clamp, weights = rn(rn(sub)*rn(sub))  (no fma)
//  - blend:    ((rn(wa*pa)+rn(wb*pb))+rn(wc*pc))+rn(wd*pd)  (no fma)
//
// Perf layout (round-8 winner): lanes 4k..4k+3 share a pixel; 2 pixels per
// thread (rows r, r+128) with 8 corner loads front-batched (MLP=8), 32-bit
// addressing, occ ~82%. New this round: __stcs streaming stores so the
// write-once output doesn't evict the gather working set from L1/L2.

static constexpr int B     = 16;
static constexpr int H     = 512;
static constexpr int W     = 512;
static constexpr int OUT_H = 256;
static constexpr int OUT_W = 256;
static constexpr int NPIX  = OUT_H * OUT_W;            // 65536
static constexpr int C4    = 4;                        // float4 quarters

__device__ __forceinline__ float4 blend_exact(float wa, float wb, float wc, float wd,
                                              float4 pa, float4 pb, float4 pc, float4 pd)
{
    float4 o;
    o.x = __fadd_rn(__fadd_rn(__fadd_rn(__fmul_rn(wa, pa.x), __fmul_rn(wb, pb.x)),
                              __fmul_rn(wc, pc.x)), __fmul_rn(wd, pd.x));
    o.y = __fadd_rn(__fadd_rn(__fadd_rn(__fmul_rn(wa, pa.y), __fmul_rn(wb, pb.y)),
                              __fmul_rn(wc, pc.y)), __fmul_rn(wd, pd.y));
    o.z = __fadd_rn(__fadd_rn(__fadd_rn(__fmul_rn(wa, pa.z), __fmul_rn(wb, pb.z)),
                              __fmul_rn(wc, pc.z)), __fmul_rn(wd, pd.z));
    o.w = __fadd_rn(__fadd_rn(__fadd_rn(__fmul_rn(wa, pa.w), __fmul_rn(wb, pb.w)),
                              __fmul_rn(wc, pc.w)), __fmul_rn(wd, pd.w));
    return o;
}

struct PixInfo {
    unsigned ia, ib, ic, id;   // float4 indices
    float wa, wb, wc, wd;
};

__device__ __forceinline__ PixInfo pixel_info(float x, float y, unsigned baseb, unsigned c4)
{
    int x0 = (int)x;           // cvt.rzi — trunc toward zero
    int y0 = (int)y;
    int x1 = x0 + 1;
    int y1 = y0 + 1;
    x0 = min(max(x0, 0), W - 1);
    x1 = min(max(x1, 0), W - 1);
    y0 = min(max(y0, 0), H - 1);
    y1 = min(max(y1, 0), H - 1);

    const float x0f = (float)x0, x1f = (float)x1;
    const float y0f = (float)y0, y1f = (float)y1;

    const float dxa = __fsub_rn(x1f, x);
    const float dxb = __fsub_rn(x, x0f);
    const float dya = __fsub_rn(y1f, y);
    const float dyb = __fsub_rn(y, y0f);

    PixInfo p;
    p.wa = __fmul_rn(dxa, dya);
    p.wb = __fmul_rn(dxa, dyb);
    p.wc = __fmul_rn(dxb, dya);
    p.wd = __fmul_rn(dxb, dyb);

    const unsigned r0 = baseb + (unsigned)y0 * W;
    const unsigned r1 = baseb + (unsigned)y1 * W;
    p.ia = (r0 + (unsigned)x0) * C4 + c4;
    p.ib = (r1 + (unsigned)x0) * C4 + c4;
    p.ic = (r0 + (unsigned)x1) * C4 + c4;
    p.id = (r1 + (unsigned)x1) * C4 + c4;
    return p;
}

__global__ __launch_bounds__(256)
void bilinear_sampler_kernel(const float* __restrict__ X,
                             const float* __restrict__ theta,
                             float* __restrict__ out)
{
    const unsigned tid = blockIdx.x * blockDim.x + threadIdx.x;
    // 2,097,152 threads; each does pixels (b, row, col) and (b, row+128, col)

    const unsigned c4  = tid & 3u;
    const unsigned idx = tid >> 2;             // [0, 524288)
    const unsigned b   = idx >> 15;            // / 32768
    const unsigned rem = idx & 32767u;
    const unsigned row = rem >> 8;             // [0, 128)
    const unsigned col = rem & 255u;
    const unsigned row2 = row + 128u;

    const float DELTA = 2.0f / 255.0f;
    const float gx  = __fadd_rn(-1.0f, __fmul_rn((float)col,  DELTA));
    const float gy0 = __fadd_rn(-1.0f, __fmul_rn((float)row,  DELTA));
    const float gy1 = __fadd_rn(-1.0f, __fmul_rn((float)row2, DELTA));

    const float* th = theta + b * 6;
    const float t0 = __ldg(th + 0), t1 = __ldg(th + 1), t2 = __ldg(th + 2);
    const float t3 = __ldg(th + 3), t4 = __ldg(th + 4), t5 = __ldg(th + 5);

    const float m0x = __fmul_rn(t0, gx);       // shared across both pixels
    const float m1x = __fmul_rn(t3, gx);

    const float sg0a = __fadd_rn(__fmaf_rn(t1, gy0, m0x), t2);
    const float sg1a = __fadd_rn(__fmaf_rn(t4, gy0, m1x), t5);
    const float sg0b = __fadd_rn(__fmaf_rn(t1, gy1, m0x), t2);
    const float sg1b = __fadd_rn(__fmaf_rn(t4, gy1, m1x), t5);

    const float xA = __fmul_rn(__fadd_rn(sg0a, 1.0f), 256.0f);
    const float yA = __fmul_rn(__fadd_rn(sg1a, 1.0f), 256.0f);
    const float xB = __fmul_rn(__fadd_rn(sg0b, 1.0f), 256.0f);
    const float yB = __fmul_rn(__fadd_rn(sg1b, 1.0f), 256.0f);

    const unsigned baseb = b * (unsigned)(H * W);
    const PixInfo A = pixel_info(xA, yA, baseb, c4);
    const PixInfo Bx = pixel_info(xB, yB, baseb, c4);

    const float4* Xf4 = (const float4*)X;

    // 8 independent loads up front (MLP=8)
    const float4 paA = __ldg(Xf4 + A.ia);
    const float4 pbA = __ldg(Xf4 + A.ib);
    const float4 pcA = __ldg(Xf4 + A.ic);
    const float4 pdA = __ldg(Xf4 + A.id);
    const float4 paB = __ldg(Xf4 + Bx.ia);
    const float4 pbB = __ldg(Xf4 + Bx.ib);
    const float4 pcB = __ldg(Xf4 + Bx.ic);
    const float4 pdB = __ldg(Xf4 + Bx.id);

    const float4 oA = blend_exact(A.wa, A.wb, A.wc, A.wd, paA, pbA, pcA, pdA);
    const float4 oB = blend_exact(Bx.wa, Bx.wb, Bx.wc, Bx.wd, paB, pbB, pcB, pdB);

    // streaming stores (evict-first): output is write-once, never re-read
    const unsigned o0 = (b * (unsigned)NPIX + row * 256u + col) * 4u + c4;
    __stcs(((float4*)out) + o0,           oA);
    __stcs(((float4*)out) + o0 + 131072u, oB);
}

extern "C" void kernel_launch(void* const* d_in, const int* in_sizes, int n_in,
                              void* d_out, int out_size)
{
    const float* X     = (const float*)d_in[0];
    const float* theta = (const float*)d_in[1];
    float* out         = (float*)d_out;

    const int total = 2097152;             // B*NPIX*C4 / 2
    const int tpb = 256;
    bilinear_sampler_kernel<<<total / tpb, tpb>>>(X, theta, out);
}